// round 5
// baseline (speedup 1.0000x reference)
#include <cuda_runtime.h>
#include <math.h>

// Problem constants
#define NPTS 4096
#define DDIM 2048
#define NCLS 128
#define MROWS 256               // stacked [meanR; meanT]
#define KSPLIT 32
#define KSLICE 64               // K per gemm block
#define NBLK_GEMM (2 * 2 * KSPLIT)
#define MARGIN 0.5f
#define GSCALE  4294967296.0    // 2^32 fixed-point scale for G accumulation
#define GINV_F  2.3283064365386963e-10f   // 2^-32

// ---------------- scratch (static device globals; no allocation) ----------------
__device__ __align__(16) float d_M[MROWS][DDIM];         // class means [R;T] (2 MB)
__device__ __align__(16) float d_C[NCLS][DDIM];          // 0.5*(R+T)         (1 MB)
__device__ __align__(16) long long d_Gq[MROWS * NCLS];   // fixed-point G     (256 KB)
__device__ float d_n2[2][NCLS][2];                       // mean-norm partials
__device__ int   d_cnt[NCLS];
__device__ int   d_done;

// ---------------- f32x2 packed-FMA helpers (sm_103a) ----------------
__device__ __forceinline__ void fma2(unsigned long long& d,
                                     unsigned long long a,
                                     unsigned long long b) {
    asm("fma.rn.f32x2 %0, %1, %2, %0;" : "+l"(d) : "l"(a), "l"(b));
}
__device__ __forceinline__ unsigned long long dup2(float x) {
    unsigned long long r;
    asm("mov.b64 %0, {%1, %1};" : "=l"(r) : "f"(x));
    return r;
}
__device__ __forceinline__ float2 unpk2(unsigned long long v) {
    float2 f;
    asm("mov.b64 {%0, %1}, %2;" : "=f"(f.x), "=f"(f.y) : "l"(v));
    return f;
}

// =====================================================================
// Kernel 1: fused setup + segment means.
// grid (NCLS, 2 col-chunks of 1024), 256 threads.
// Each block: (a) zeroes its slice of d_Gq / resets d_done,
// (b) compacts its class's row list in-block (deterministic order),
// (c) streams its 1024-col slice of both inputs (64 MB total chip-wide),
// (d) writes means M, centers C, mean-norm partials, class counts.
// =====================================================================
__global__ void segmean_kernel(const float* __restrict__ m1,
                               const float* __restrict__ m2,
                               const int* __restrict__ tgt) {
    const int c     = blockIdx.x;
    const int chunk = blockIdx.y;
    const int tid   = threadIdx.x;
    const int lane  = tid & 31, wid = tid >> 5;

    __shared__ short s_rows[NPTS];   // worst-case capacity (8 KB)
    __shared__ int   s_wtot[8];
    __shared__ float s_wr[8], s_wt[8];

    // (a) zero this block's 128-entry slice of d_Gq; reset arrival counter
    {
        long long* g = d_Gq + (chunk * NCLS + c) * 128;
        if (tid < 128) g[tid] = 0LL;
    }
    if (c == 0 && chunk == 0 && tid == 0) d_done = 0;

    // (b) compaction: thread owns 16 contiguous rows
    const int base = tid * 16;
    int cl = 0;
    #pragma unroll
    for (int j = 0; j < 16; j++) cl += (tgt[base + j] == c);

    int incl = cl;                                   // warp inclusive scan
    #pragma unroll
    for (int o = 1; o < 32; o <<= 1) {
        int v = __shfl_up_sync(0xffffffffu, incl, o);
        if (lane >= o) incl += v;
    }
    if (lane == 31) s_wtot[wid] = incl;
    __syncthreads();
    int wbase = 0, cnt = 0;
    #pragma unroll
    for (int w = 0; w < 8; w++) {
        if (w < wid) wbase += s_wtot[w];
        cnt += s_wtot[w];
    }
    int off = wbase + incl - cl;                     // exclusive offset
    #pragma unroll
    for (int j = 0; j < 16; j++)
        if (tgt[base + j] == c) s_rows[off++] = (short)(base + j);
    __syncthreads();

    if (chunk == 0 && tid == 0) d_cnt[c] = cnt;

    // (c) stream: each thread one float4 column group
    const int col = chunk * 1024 + tid * 4;
    float4 aR = make_float4(0.f, 0.f, 0.f, 0.f);
    float4 aT = make_float4(0.f, 0.f, 0.f, 0.f);
    #pragma unroll 4
    for (int j = 0; j < cnt; j++) {
        int b = s_rows[j] * DDIM + col;
        float4 x = *(const float4*)(m1 + b);
        float4 y = *(const float4*)(m2 + b);
        aR.x += x.x; aR.y += x.y; aR.z += x.z; aR.w += x.w;
        aT.x += y.x; aT.y += y.y; aT.z += y.z; aT.w += y.w;
    }
    const float inv = 1.0f / fmaxf((float)cnt, 1.0f);
    aR.x *= inv; aR.y *= inv; aR.z *= inv; aR.w *= inv;
    aT.x *= inv; aT.y *= inv; aT.z *= inv; aT.w *= inv;

    *(float4*)&d_M[c][col]        = aR;
    *(float4*)&d_M[NCLS + c][col] = aT;
    float4 cc = make_float4(0.5f * (aR.x + aT.x), 0.5f * (aR.y + aT.y),
                            0.5f * (aR.z + aT.z), 0.5f * (aR.w + aT.w));
    *(float4*)&d_C[c][col] = cc;

    // (d) mean-norm partials
    float nR = aR.x * aR.x + aR.y * aR.y + aR.z * aR.z + aR.w * aR.w;
    float nT = aT.x * aT.x + aT.y * aT.y + aT.z * aT.z + aT.w * aT.w;
    #pragma unroll
    for (int o = 16; o > 0; o >>= 1) {
        nR += __shfl_down_sync(0xffffffffu, nR, o);
        nT += __shfl_down_sync(0xffffffffu, nT, o);
    }
    if (lane == 0) { s_wr[wid] = nR; s_wt[wid] = nT; }
    __syncthreads();
    if (tid == 0) {
        float r = 0.f, t = 0.f;
        #pragma unroll
        for (int w = 0; w < 8; w++) { r += s_wr[w]; t += s_wt[w]; }
        d_n2[0][c][chunk] = r;
        d_n2[1][c][chunk] = t;
    }
}

// =====================================================================
// Kernel 2: fused GEMM + loss.
// grid (2 row-tiles, 2 col-tiles, KSPLIT) = 128 blocks (1 wave), 256 thr.
// GEMM: 128x64 tile, 8x4 micro-tile, packed fma.rn.f32x2 on row pairs,
// K-split reduced via order-independent i64 fixed-point atomics.
// Last-arriving block computes the class-pair loss from L2-resident G.
// =====================================================================
__global__ void gemm_loss_kernel(float* __restrict__ out) {
    const int tid = threadIdx.x;
    const int tx = tid & 15, ty = tid >> 4;
    const int row0 = blockIdx.x * 128;      // into d_M
    const int col0 = blockIdx.y * 64;       // into d_C
    const int kb   = blockIdx.z * KSLICE;

    __shared__ union {
        float As[KSLICE][128];              // [k][row], 32 KB (dead after gemm)
        int   last;
    } sA;
    __shared__ union {
        float Bs[KSLICE][64];               // [k][col], 16 KB (dead after gemm)
        struct {
            float cb2[NCLS], ra2[NCLS], ta2[NCLS], cw[NCLS];
            float red[256];
        } l;
    } sB;

    // cooperative transposed loads (lane varies over row -> conflict-free STS)
    #pragma unroll
    for (int it = 0; it < 8; it++) {
        int t = it * 256 + tid;
        int r = t & 127, q = t >> 7;        // q: float4 index in k
        float4 a = *(const float4*)&d_M[row0 + r][kb + q * 4];
        sA.As[q * 4 + 0][r] = a.x; sA.As[q * 4 + 1][r] = a.y;
        sA.As[q * 4 + 2][r] = a.z; sA.As[q * 4 + 3][r] = a.w;
    }
    #pragma unroll
    for (int it = 0; it < 4; it++) {
        int t = it * 256 + tid;
        int r = t & 63, q = t >> 6;
        float4 b = *(const float4*)&d_C[col0 + r][kb + q * 4];
        sB.Bs[q * 4 + 0][r] = b.x; sB.Bs[q * 4 + 1][r] = b.y;
        sB.Bs[q * 4 + 2][r] = b.z; sB.Bs[q * 4 + 3][r] = b.w;
    }
    __syncthreads();

    unsigned long long acc2[4][4];          // [row-pair][col], packed f32x2
    #pragma unroll
    for (int i = 0; i < 4; i++)
        #pragma unroll
        for (int j = 0; j < 4; j++) acc2[i][j] = 0ULL;

    const int ty8 = ty * 8;
    #pragma unroll 8
    for (int k = 0; k < KSLICE; k++) {
        float4 bv = *(const float4*)&sB.Bs[k][tx * 4];
        unsigned long long b0 = dup2(bv.x), b1 = dup2(bv.y);
        unsigned long long b2 = dup2(bv.z), b3 = dup2(bv.w);
        #pragma unroll
        for (int rp = 0; rp < 4; rp++) {
            unsigned long long a01 =
                *(const unsigned long long*)&sA.As[k][ty8 + rp * 2];
            fma2(acc2[rp][0], a01, b0);
            fma2(acc2[rp][1], a01, b1);
            fma2(acc2[rp][2], a01, b2);
            fma2(acc2[rp][3], a01, b3);
        }
    }

    // epilogue: deterministic fixed-point accumulation into G
    #pragma unroll
    for (int rp = 0; rp < 4; rp++)
        #pragma unroll
        for (int ci = 0; ci < 4; ci++) {
            float2 v = unpk2(acc2[rp][ci]);
            int r = row0 + ty8 + rp * 2;
            int cc = col0 + tx * 4 + ci;
            atomicAdd((unsigned long long*)&d_Gq[r * NCLS + cc],
                      (unsigned long long)__double2ll_rn((double)v.x * GSCALE));
            atomicAdd((unsigned long long*)&d_Gq[(r + 1) * NCLS + cc],
                      (unsigned long long)__double2ll_rn((double)v.y * GSCALE));
        }

    // ---- last-block loss tail (threadFenceReduction pattern) ----
    __threadfence();
    __syncthreads();                         // As/Bs now dead
    if (tid == 0)
        sA.last = (atomicAdd(&d_done, 1) == NBLK_GEMM - 1) ? 1 : 0;
    __syncthreads();
    if (!sA.last) return;
    __threadfence();

    if (tid < NCLS) {
        int b = tid;
        float g_rb = (float)d_Gq[b * NCLS + b] * GINV_F;
        float g_tb = (float)d_Gq[(NCLS + b) * NCLS + b] * GINV_F;
        sB.l.cb2[b] = 0.5f * (g_rb + g_tb);            // ||C_b||^2
        sB.l.ra2[b] = d_n2[0][b][0] + d_n2[0][b][1];   // ||R_b||^2
        sB.l.ta2[b] = d_n2[1][b][0] + d_n2[1][b][1];   // ||T_b||^2
        sB.l.cw[b]  = (float)d_cnt[b];
    }
    __syncthreads();

    float facc = 0.f;
    #pragma unroll 4
    for (int i = 0; i < 32; i++) {
        int p = i * 512 + tid * 2;           // even pair index
        int a = p >> 7, b = p & (NCLS - 1);  // b even
        longlong2 q1 = *(const longlong2*)&d_Gq[a * NCLS + b];
        longlong2 q2 = *(const longlong2*)&d_Gq[(NCLS + a) * NCLS + b];
        #pragma unroll
        for (int e = 0; e < 2; e++) {
            int bb = b + e;
            float g1 = (float)(e ? q1.y : q1.x) * GINV_F;
            float g2 = (float)(e ? q2.y : q2.x) * GINV_F;
            float sq1 = fmaxf(sB.l.ra2[a] + sB.l.cb2[bb] - 2.f * g1, 1e-12f);
            float sq2 = fmaxf(sB.l.ta2[a] + sB.l.cb2[bb] - 2.f * g2, 1e-12f);
            float term;
            if (a == bb) {
                term = sq1 + sq2;                        // label=1: dist^2
            } else {
                float dd1 = sqrtf(sqrtf(sq1) + 1e-10f);  // sqrt of sqrt
                float dd2 = sqrtf(sqrtf(sq2) + 1e-10f);
                float h1 = fmaxf(MARGIN - dd1, 0.f);
                float h2 = fmaxf(MARGIN - dd2, 0.f);
                term = h1 * h1 + h2 * h2;
            }
            facc += sB.l.cw[a] * sB.l.cw[bb] * term;
        }
    }

    sB.l.red[tid] = facc;
    __syncthreads();
    #pragma unroll
    for (int s = 128; s > 0; s >>= 1) {
        if (tid < s) sB.l.red[tid] += sB.l.red[tid + s];
        __syncthreads();
    }
    if (tid == 0)
        out[0] = sB.l.red[0] * (1.0f / ((float)NPTS * (float)NPTS));
}

// =====================================================================
// kernel_launch: graph-capturable, allocation-free, 2 kernels.
// inputs: [0] modal1 (N*D f32), [1] modal2 (N*D f32), [2] targets (N i32)
// output: scalar f32
// =====================================================================
extern "C" void kernel_launch(void* const* d_in, const int* in_sizes, int n_in,
                              void* d_out, int out_size) {
    (void)in_sizes; (void)n_in; (void)out_size;
    const float* m1  = (const float*)d_in[0];
    const float* m2  = (const float*)d_in[1];
    const int*   tgt = (const int*)d_in[2];
    float* out = (float*)d_out;

    segmean_kernel<<<dim3(NCLS, 2), 256>>>(m1, m2, tgt);
    gemm_loss_kernel<<<dim3(2, 2, KSPLIT), 256>>>(out);
}

// round 9
// speedup vs baseline: 1.4413x; 1.4413x over previous
#include <cuda_runtime.h>
#include <math.h>

// Problem constants
#define NPTS 4096
#define DDIM 2048
#define NCLS 128
#define MROWS 256               // stacked [meanR; meanT]
#define KSPLIT 32
#define KSLICE 64               // K per gemm block
#define NBLK_GEMM (4 * 2 * KSPLIT)   // 256 blocks
#define MARGIN 0.5f
#define GSCALE  4294967296.0    // 2^32 fixed-point scale for G accumulation
#define GINV_F  2.3283064365386963e-10f   // 2^-32

// ---------------- scratch (static device globals; no allocation) ----------------
__device__ __align__(16) float d_M[MROWS][DDIM];         // class means [R;T] (2 MB)
__device__ __align__(16) float d_C[NCLS][DDIM];          // 0.5*(R+T)         (1 MB)
__device__ __align__(16) long long d_Gq[MROWS * NCLS];   // fixed-point G     (256 KB)
__device__ float d_n2[2][NCLS][2];                       // mean-norm partials
__device__ int   d_cnt[NCLS];
__device__ int   d_done;

// =====================================================================
// Kernel 1: fused setup + segment means.
// grid (NCLS, 2 col-chunks of 1024), 256 threads.
// Each block: (a) zeroes its slice of d_Gq / resets d_done,
// (b) compacts its class's row list in-block (deterministic order),
// (c) streams its 1024-col slice of both inputs (64 MB total chip-wide),
// (d) writes means M, centers C, mean-norm partials, class counts.
// =====================================================================
__global__ void segmean_kernel(const float* __restrict__ m1,
                               const float* __restrict__ m2,
                               const int* __restrict__ tgt) {
    const int c     = blockIdx.x;
    const int chunk = blockIdx.y;
    const int tid   = threadIdx.x;
    const int lane  = tid & 31, wid = tid >> 5;

    __shared__ short s_rows[NPTS];   // worst-case capacity (8 KB)
    __shared__ int   s_wtot[8];
    __shared__ float s_wr[8], s_wt[8];

    // (a) zero this block's 128-entry slice of d_Gq; reset arrival counter
    {
        long long* g = d_Gq + (chunk * NCLS + c) * 128;
        if (tid < 128) g[tid] = 0LL;
    }
    if (c == 0 && chunk == 0 && tid == 0) d_done = 0;

    // (b) compaction: thread owns 16 contiguous rows
    const int base = tid * 16;
    int cl = 0;
    #pragma unroll
    for (int j = 0; j < 16; j++) cl += (tgt[base + j] == c);

    int incl = cl;                                   // warp inclusive scan
    #pragma unroll
    for (int o = 1; o < 32; o <<= 1) {
        int v = __shfl_up_sync(0xffffffffu, incl, o);
        if (lane >= o) incl += v;
    }
    if (lane == 31) s_wtot[wid] = incl;
    __syncthreads();
    int wbase = 0, cnt = 0;
    #pragma unroll
    for (int w = 0; w < 8; w++) {
        if (w < wid) wbase += s_wtot[w];
        cnt += s_wtot[w];
    }
    int off = wbase + incl - cl;                     // exclusive offset
    #pragma unroll
    for (int j = 0; j < 16; j++)
        if (tgt[base + j] == c) s_rows[off++] = (short)(base + j);
    __syncthreads();

    if (chunk == 0 && tid == 0) d_cnt[c] = cnt;

    // (c) stream: each thread one float4 column group
    const int col = chunk * 1024 + tid * 4;
    float4 aR = make_float4(0.f, 0.f, 0.f, 0.f);
    float4 aT = make_float4(0.f, 0.f, 0.f, 0.f);
    #pragma unroll 4
    for (int j = 0; j < cnt; j++) {
        int b = s_rows[j] * DDIM + col;
        float4 x = *(const float4*)(m1 + b);
        float4 y = *(const float4*)(m2 + b);
        aR.x += x.x; aR.y += x.y; aR.z += x.z; aR.w += x.w;
        aT.x += y.x; aT.y += y.y; aT.z += y.z; aT.w += y.w;
    }
    const float inv = 1.0f / fmaxf((float)cnt, 1.0f);
    aR.x *= inv; aR.y *= inv; aR.z *= inv; aR.w *= inv;
    aT.x *= inv; aT.y *= inv; aT.z *= inv; aT.w *= inv;

    *(float4*)&d_M[c][col]        = aR;
    *(float4*)&d_M[NCLS + c][col] = aT;
    float4 cc = make_float4(0.5f * (aR.x + aT.x), 0.5f * (aR.y + aT.y),
                            0.5f * (aR.z + aT.z), 0.5f * (aR.w + aT.w));
    *(float4*)&d_C[c][col] = cc;

    // (d) mean-norm partials
    float nR = aR.x * aR.x + aR.y * aR.y + aR.z * aR.z + aR.w * aR.w;
    float nT = aT.x * aT.x + aT.y * aT.y + aT.z * aT.z + aT.w * aT.w;
    #pragma unroll
    for (int o = 16; o > 0; o >>= 1) {
        nR += __shfl_down_sync(0xffffffffu, nR, o);
        nT += __shfl_down_sync(0xffffffffu, nT, o);
    }
    if (lane == 0) { s_wr[wid] = nR; s_wt[wid] = nT; }
    __syncthreads();
    if (tid == 0) {
        float r = 0.f, t = 0.f;
        #pragma unroll
        for (int w = 0; w < 8; w++) { r += s_wr[w]; t += s_wt[w]; }
        d_n2[0][c][chunk] = r;
        d_n2[1][c][chunk] = t;
    }
}

// =====================================================================
// Kernel 2: fused GEMM + loss (scalar-FFMA core, proven in R3/R4).
// grid (4 row-tiles, 2 col-tiles, KSPLIT) = 256 blocks, 256 threads.
// GEMM: 64x64 tile, 4x4 register micro-tile, K-major smem
// (conflict-free float4 LDS). K-split reduced via order-independent
// i64 fixed-point atomics -> deterministic across graph replays.
// Last-arriving block computes the class-pair loss from L2-resident G.
// =====================================================================
__global__ void gemm_loss_kernel(float* __restrict__ out) {
    const int tid = threadIdx.x;
    const int tx = tid & 15, ty = tid >> 4;
    const int row0 = blockIdx.x * 64;       // into d_M (0..192)
    const int col0 = blockIdx.y * 64;       // into d_C (0 or 64)
    const int kb   = blockIdx.z * KSLICE;   // 64-wide K slice

    __shared__ union {
        float As[KSLICE][64];               // [k][row], 16 KB (dead after gemm)
        int   last;
    } sA;
    __shared__ union {
        float Bs[KSLICE][64];               // [k][col], 16 KB (dead after gemm)
        struct {
            float cb2[NCLS], ra2[NCLS], ta2[NCLS], cw[NCLS];
            float red[256];
        } l;
    } sB;

    float acc[4][4];
    #pragma unroll
    for (int i = 0; i < 4; i++)
        #pragma unroll
        for (int j = 0; j < 4; j++) acc[i][j] = 0.f;

    // cooperative transposed load (r varies over lanes -> conflict-free STS)
    #pragma unroll
    for (int it = 0; it < 4; it++) {
        int t = tid + it * 256;     // 0..1023
        int r = t & 63;
        int q = t >> 6;             // float4 index in k (0..15)
        float4 a = *(const float4*)&d_M[row0 + r][kb + q * 4];
        sA.As[q * 4 + 0][r] = a.x; sA.As[q * 4 + 1][r] = a.y;
        sA.As[q * 4 + 2][r] = a.z; sA.As[q * 4 + 3][r] = a.w;
        float4 b = *(const float4*)&d_C[col0 + r][kb + q * 4];
        sB.Bs[q * 4 + 0][r] = b.x; sB.Bs[q * 4 + 1][r] = b.y;
        sB.Bs[q * 4 + 2][r] = b.z; sB.Bs[q * 4 + 3][r] = b.w;
    }
    __syncthreads();

    #pragma unroll 16
    for (int k = 0; k < KSLICE; k++) {
        float4 av = *(const float4*)&sA.As[k][ty * 4];
        float4 bv = *(const float4*)&sB.Bs[k][tx * 4];
        acc[0][0] += av.x * bv.x; acc[0][1] += av.x * bv.y;
        acc[0][2] += av.x * bv.z; acc[0][3] += av.x * bv.w;
        acc[1][0] += av.y * bv.x; acc[1][1] += av.y * bv.y;
        acc[1][2] += av.y * bv.z; acc[1][3] += av.y * bv.w;
        acc[2][0] += av.z * bv.x; acc[2][1] += av.z * bv.y;
        acc[2][2] += av.z * bv.z; acc[2][3] += av.z * bv.w;
        acc[3][0] += av.w * bv.x; acc[3][1] += av.w * bv.y;
        acc[3][2] += av.w * bv.z; acc[3][3] += av.w * bv.w;
    }

    // epilogue: deterministic fixed-point accumulation into G
    #pragma unroll
    for (int i = 0; i < 4; i++)
        #pragma unroll
        for (int j = 0; j < 4; j++) {
            long long q = __double2ll_rn((double)acc[i][j] * GSCALE);
            atomicAdd((unsigned long long*)
                          &d_Gq[(row0 + ty * 4 + i) * NCLS + (col0 + tx * 4 + j)],
                      (unsigned long long)q);
        }

    // ---- last-block loss tail (threadFenceReduction pattern) ----
    __threadfence();
    __syncthreads();                         // As/Bs now dead
    if (tid == 0)
        sA.last = (atomicAdd(&d_done, 1) == NBLK_GEMM - 1) ? 1 : 0;
    __syncthreads();
    if (!sA.last) return;
    __threadfence();

    if (tid < NCLS) {
        int b = tid;
        float g_rb = (float)d_Gq[b * NCLS + b] * GINV_F;
        float g_tb = (float)d_Gq[(NCLS + b) * NCLS + b] * GINV_F;
        sB.l.cb2[b] = 0.5f * (g_rb + g_tb);            // ||C_b||^2
        sB.l.ra2[b] = d_n2[0][b][0] + d_n2[0][b][1];   // ||R_b||^2
        sB.l.ta2[b] = d_n2[1][b][0] + d_n2[1][b][1];   // ||T_b||^2
        sB.l.cw[b]  = (float)d_cnt[b];
    }
    __syncthreads();

    float facc = 0.f;
    #pragma unroll 4
    for (int i = 0; i < 32; i++) {
        int p = i * 512 + tid * 2;           // even pair index
        int a = p >> 7, b = p & (NCLS - 1);  // b even
        longlong2 q1 = *(const longlong2*)&d_Gq[a * NCLS + b];
        longlong2 q2 = *(const longlong2*)&d_Gq[(NCLS + a) * NCLS + b];
        #pragma unroll
        for (int e = 0; e < 2; e++) {
            int bb = b + e;
            float g1 = (float)(e ? q1.y : q1.x) * GINV_F;
            float g2 = (float)(e ? q2.y : q2.x) * GINV_F;
            float sq1 = fmaxf(sB.l.ra2[a] + sB.l.cb2[bb] - 2.f * g1, 1e-12f);
            float sq2 = fmaxf(sB.l.ta2[a] + sB.l.cb2[bb] - 2.f * g2, 1e-12f);
            float term;
            if (a == bb) {
                term = sq1 + sq2;                        // label=1: dist^2
            } else {
                float dd1 = sqrtf(sqrtf(sq1) + 1e-10f);  // sqrt of sqrt
                float dd2 = sqrtf(sqrtf(sq2) + 1e-10f);
                float h1 = fmaxf(MARGIN - dd1, 0.f);
                float h2 = fmaxf(MARGIN - dd2, 0.f);
                term = h1 * h1 + h2 * h2;
            }
            facc += sB.l.cw[a] * sB.l.cw[bb] * term;
        }
    }

    sB.l.red[tid] = facc;
    __syncthreads();
    #pragma unroll
    for (int s = 128; s > 0; s >>= 1) {
        if (tid < s) sB.l.red[tid] += sB.l.red[tid + s];
        __syncthreads();
    }
    if (tid == 0)
        out[0] = sB.l.red[0] * (1.0f / ((float)NPTS * (float)NPTS));
}

// =====================================================================
// kernel_launch: graph-capturable, allocation-free, 2 kernels.
// inputs: [0] modal1 (N*D f32), [1] modal2 (N*D f32), [2] targets (N i32)
// output: scalar f32
// =====================================================================
extern "C" void kernel_launch(void* const* d_in, const int* in_sizes, int n_in,
                              void* d_out, int out_size) {
    (void)in_sizes; (void)n_in; (void)out_size;
    const float* m1  = (const float*)d_in[0];
    const float* m2  = (const float*)d_in[1];
    const int*   tgt = (const int*)d_in[2];
    float* out = (float*)d_out;

    segmean_kernel<<<dim3(NCLS, 2), 256>>>(m1, m2, tgt);
    gemm_loss_kernel<<<dim3(4, 2, KSPLIT), 256>>>(out);
}

// round 10
// speedup vs baseline: 1.4822x; 1.0284x over previous
#include <cuda_runtime.h>
#include <math.h>

// Problem constants
#define NPTS 4096
#define DDIM 2048
#define NCLS 128
#define MROWS 256               // stacked [meanR; meanT]
#define KSPLIT 32
#define KSLICE 64               // K per gemm block
#define NBLK_GEMM (4 * 2 * KSPLIT)   // 256 blocks
#define MARGIN 0.5f
#define GSCALE_F 4294967296.0f  // 2^32 fixed-point scale (float; NO fp64 anywhere hot)
#define GINV_F  2.3283064365386963e-10f   // 2^-32

// ---------------- scratch (static device globals; no allocation) ----------------
__device__ __align__(16) float d_M[MROWS][DDIM];         // class means [R;T] (2 MB)
__device__ __align__(16) float d_C[NCLS][DDIM];          // 0.5*(R+T)         (1 MB)
__device__ __align__(16) long long d_Gq[MROWS * NCLS];   // fixed-point G     (256 KB)
__device__ float d_n2[2][NCLS][2];                       // mean-norm partials
__device__ int   d_cnt[NCLS];
__device__ int   d_done;

// =====================================================================
// Kernel 1: fused setup + segment means.
// grid (NCLS, 2 col-chunks of 1024), 256 threads.
// Each block: (a) zeroes its slice of d_Gq / resets d_done,
// (b) compacts its class's row list in-block (deterministic order),
// (c) streams its 1024-col slice of both inputs (64 MB total chip-wide),
// (d) writes means M, centers C, mean-norm partials, class counts.
// =====================================================================
__global__ void segmean_kernel(const float* __restrict__ m1,
                               const float* __restrict__ m2,
                               const int* __restrict__ tgt) {
    const int c     = blockIdx.x;
    const int chunk = blockIdx.y;
    const int tid   = threadIdx.x;
    const int lane  = tid & 31, wid = tid >> 5;

    __shared__ short s_rows[NPTS];   // worst-case capacity (8 KB)
    __shared__ int   s_wtot[8];
    __shared__ float s_wr[8], s_wt[8];

    // (a) zero this block's 128-entry slice of d_Gq; reset arrival counter
    {
        long long* g = d_Gq + (chunk * NCLS + c) * 128;
        if (tid < 128) g[tid] = 0LL;
    }
    if (c == 0 && chunk == 0 && tid == 0) d_done = 0;

    // (b) compaction: thread owns 16 contiguous rows
    const int base = tid * 16;
    int cl = 0;
    #pragma unroll
    for (int j = 0; j < 16; j++) cl += (tgt[base + j] == c);

    int incl = cl;                                   // warp inclusive scan
    #pragma unroll
    for (int o = 1; o < 32; o <<= 1) {
        int v = __shfl_up_sync(0xffffffffu, incl, o);
        if (lane >= o) incl += v;
    }
    if (lane == 31) s_wtot[wid] = incl;
    __syncthreads();
    int wbase = 0, cnt = 0;
    #pragma unroll
    for (int w = 0; w < 8; w++) {
        if (w < wid) wbase += s_wtot[w];
        cnt += s_wtot[w];
    }
    int off = wbase + incl - cl;                     // exclusive offset
    #pragma unroll
    for (int j = 0; j < 16; j++)
        if (tgt[base + j] == c) s_rows[off++] = (short)(base + j);
    __syncthreads();

    if (chunk == 0 && tid == 0) d_cnt[c] = cnt;

    // (c) stream: each thread one float4 column group
    const int col = chunk * 1024 + tid * 4;
    float4 aR = make_float4(0.f, 0.f, 0.f, 0.f);
    float4 aT = make_float4(0.f, 0.f, 0.f, 0.f);
    #pragma unroll 4
    for (int j = 0; j < cnt; j++) {
        int b = s_rows[j] * DDIM + col;
        float4 x = *(const float4*)(m1 + b);
        float4 y = *(const float4*)(m2 + b);
        aR.x += x.x; aR.y += x.y; aR.z += x.z; aR.w += x.w;
        aT.x += y.x; aT.y += y.y; aT.z += y.z; aT.w += y.w;
    }
    const float inv = 1.0f / fmaxf((float)cnt, 1.0f);
    aR.x *= inv; aR.y *= inv; aR.z *= inv; aR.w *= inv;
    aT.x *= inv; aT.y *= inv; aT.z *= inv; aT.w *= inv;

    *(float4*)&d_M[c][col]        = aR;
    *(float4*)&d_M[NCLS + c][col] = aT;
    float4 cc = make_float4(0.5f * (aR.x + aT.x), 0.5f * (aR.y + aT.y),
                            0.5f * (aR.z + aT.z), 0.5f * (aR.w + aT.w));
    *(float4*)&d_C[c][col] = cc;

    // (d) mean-norm partials
    float nR = aR.x * aR.x + aR.y * aR.y + aR.z * aR.z + aR.w * aR.w;
    float nT = aT.x * aT.x + aT.y * aT.y + aT.z * aT.z + aT.w * aT.w;
    #pragma unroll
    for (int o = 16; o > 0; o >>= 1) {
        nR += __shfl_down_sync(0xffffffffu, nR, o);
        nT += __shfl_down_sync(0xffffffffu, nT, o);
    }
    if (lane == 0) { s_wr[wid] = nR; s_wt[wid] = nT; }
    __syncthreads();
    if (tid == 0) {
        float r = 0.f, t = 0.f;
        #pragma unroll
        for (int w = 0; w < 8; w++) { r += s_wr[w]; t += s_wt[w]; }
        d_n2[0][c][chunk] = r;
        d_n2[1][c][chunk] = t;
    }
}

// =====================================================================
// Kernel 2: fused GEMM + loss (scalar-FFMA core; float-only epilogue).
// grid (4 row-tiles, 2 col-tiles, KSPLIT) = 256 blocks, 256 threads.
// GEMM: 64x64 tile, 4x4 register micro-tile, K-major smem
// (conflict-free float4 LDS). K-split reduced via order-independent
// i64 fixed-point atomics (llrintf quantization -> zero fp64 ops).
// Last-arriving block computes the class-pair loss from L2-resident G.
// =====================================================================
__global__ void gemm_loss_kernel(float* __restrict__ out) {
    const int tid = threadIdx.x;
    const int tx = tid & 15, ty = tid >> 4;
    const int row0 = blockIdx.x * 64;       // into d_M (0..192)
    const int col0 = blockIdx.y * 64;       // into d_C (0 or 64)
    const int kb   = blockIdx.z * KSLICE;   // 64-wide K slice

    __shared__ union {
        float As[KSLICE][64];               // [k][row], 16 KB (dead after gemm)
        int   last;
    } sA;
    __shared__ union {
        float Bs[KSLICE][64];               // [k][col], 16 KB (dead after gemm)
        struct {
            float cb2[NCLS], ra2[NCLS], ta2[NCLS], cw[NCLS];
            float red[256];
        } l;
    } sB;

    float acc[4][4];
    #pragma unroll
    for (int i = 0; i < 4; i++)
        #pragma unroll
        for (int j = 0; j < 4; j++) acc[i][j] = 0.f;

    // cooperative transposed load (r varies over lanes -> conflict-free STS)
    #pragma unroll
    for (int it = 0; it < 4; it++) {
        int t = tid + it * 256;     // 0..1023
        int r = t & 63;
        int q = t >> 6;             // float4 index in k (0..15)
        float4 a = *(const float4*)&d_M[row0 + r][kb + q * 4];
        sA.As[q * 4 + 0][r] = a.x; sA.As[q * 4 + 1][r] = a.y;
        sA.As[q * 4 + 2][r] = a.z; sA.As[q * 4 + 3][r] = a.w;
        float4 b = *(const float4*)&d_C[col0 + r][kb + q * 4];
        sB.Bs[q * 4 + 0][r] = b.x; sB.Bs[q * 4 + 1][r] = b.y;
        sB.Bs[q * 4 + 2][r] = b.z; sB.Bs[q * 4 + 3][r] = b.w;
    }
    __syncthreads();

    #pragma unroll 16
    for (int k = 0; k < KSLICE; k++) {
        float4 av = *(const float4*)&sA.As[k][ty * 4];
        float4 bv = *(const float4*)&sB.Bs[k][tx * 4];
        acc[0][0] += av.x * bv.x; acc[0][1] += av.x * bv.y;
        acc[0][2] += av.x * bv.z; acc[0][3] += av.x * bv.w;
        acc[1][0] += av.y * bv.x; acc[1][1] += av.y * bv.y;
        acc[1][2] += av.y * bv.z; acc[1][3] += av.y * bv.w;
        acc[2][0] += av.z * bv.x; acc[2][1] += av.z * bv.y;
        acc[2][2] += av.z * bv.z; acc[2][3] += av.z * bv.w;
        acc[3][0] += av.w * bv.x; acc[3][1] += av.w * bv.y;
        acc[3][2] += av.w * bv.z; acc[3][3] += av.w * bv.w;
    }

    // epilogue: deterministic fixed-point accumulation into G.
    // FLOAT-ONLY quantization: FMUL + F2I (llrintf). No fp64.
    #pragma unroll
    for (int i = 0; i < 4; i++)
        #pragma unroll
        for (int j = 0; j < 4; j++) {
            long long q = llrintf(acc[i][j] * GSCALE_F);
            atomicAdd((unsigned long long*)
                          &d_Gq[(row0 + ty * 4 + i) * NCLS + (col0 + tx * 4 + j)],
                      (unsigned long long)q);
        }

    // ---- last-block loss tail (threadFenceReduction pattern) ----
    __threadfence();
    __syncthreads();                         // As/Bs now dead
    if (tid == 0)
        sA.last = (atomicAdd(&d_done, 1) == NBLK_GEMM - 1) ? 1 : 0;
    __syncthreads();
    if (!sA.last) return;
    __threadfence();

    if (tid < NCLS) {
        int b = tid;
        float g_rb = (float)d_Gq[b * NCLS + b] * GINV_F;
        float g_tb = (float)d_Gq[(NCLS + b) * NCLS + b] * GINV_F;
        sB.l.cb2[b] = 0.5f * (g_rb + g_tb);            // ||C_b||^2
        sB.l.ra2[b] = d_n2[0][b][0] + d_n2[0][b][1];   // ||R_b||^2
        sB.l.ta2[b] = d_n2[1][b][0] + d_n2[1][b][1];   // ||T_b||^2
        sB.l.cw[b]  = (float)d_cnt[b];
    }
    __syncthreads();

    float facc = 0.f;
    #pragma unroll 4
    for (int i = 0; i < 32; i++) {
        int p = i * 512 + tid * 2;           // even pair index
        int a = p >> 7, b = p & (NCLS - 1);  // b even
        longlong2 q1 = *(const longlong2*)&d_Gq[a * NCLS + b];
        longlong2 q2 = *(const longlong2*)&d_Gq[(NCLS + a) * NCLS + b];
        #pragma unroll
        for (int e = 0; e < 2; e++) {
            int bb = b + e;
            float g1 = (float)(e ? q1.y : q1.x) * GINV_F;
            float g2 = (float)(e ? q2.y : q2.x) * GINV_F;
            float sq1 = fmaxf(sB.l.ra2[a] + sB.l.cb2[bb] - 2.f * g1, 1e-12f);
            float sq2 = fmaxf(sB.l.ta2[a] + sB.l.cb2[bb] - 2.f * g2, 1e-12f);
            float term;
            if (a == bb) {
                term = sq1 + sq2;                        // label=1: dist^2
            } else {
                float dd1 = sqrtf(sqrtf(sq1) + 1e-10f);  // sqrt of sqrt
                float dd2 = sqrtf(sqrtf(sq2) + 1e-10f);
                float h1 = fmaxf(MARGIN - dd1, 0.f);
                float h2 = fmaxf(MARGIN - dd2, 0.f);
                term = h1 * h1 + h2 * h2;
            }
            facc += sB.l.cw[a] * sB.l.cw[bb] * term;
        }
    }

    sB.l.red[tid] = facc;
    __syncthreads();
    #pragma unroll
    for (int s = 128; s > 0; s >>= 1) {
        if (tid < s) sB.l.red[tid] += sB.l.red[tid + s];
        __syncthreads();
    }
    if (tid == 0)
        out[0] = sB.l.red[0] * (1.0f / ((float)NPTS * (float)NPTS));
}

// =====================================================================
// kernel_launch: graph-capturable, allocation-free, 2 kernels.
// inputs: [0] modal1 (N*D f32), [1] modal2 (N*D f32), [2] targets (N i32)
// output: scalar f32
// =====================================================================
extern "C" void kernel_launch(void* const* d_in, const int* in_sizes, int n_in,
                              void* d_out, int out_size) {
    (void)in_sizes; (void)n_in; (void)out_size;
    const float* m1  = (const float*)d_in[0];
    const float* m2  = (const float*)d_in[1];
    const int*   tgt = (const int*)d_in[2];
    float* out = (float*)d_out;

    segmean_kernel<<<dim3(NCLS, 2), 256>>>(m1, m2, tgt);
    gemm_loss_kernel<<<dim3(4, 2, KSPLIT), 256>>>(out);
}